// round 12
// baseline (speedup 1.0000x reference)
#include <cuda_runtime.h>
#include <stdint.h>

// out[j] = (|bits[j % 4096]| > 0.5) ? 1.0f : 0.0f for all j in [0, 48*2^20).
// 192 MiB output = 16 KB-periodic pattern. Build pattern in SMEM, blast to
// GMEM with TMA bulk stores. Binding resource is AGGREGATE L2 throughput:
// ingress write stream + victim writeback to DRAM. Mitigate writeback by
// splitting the output: first half stored with L2::evict_last (retained
// across graph replays -> re-dirtied in place, no DRAM drain), second half
// with L2::evict_first (streams through without evicting the resident half).

static constexpr int THREADS     = 512;
static constexpr int BLOCKS      = 152;              // one block per SM
static constexpr int PAT4        = 1024;             // 16 KB pattern in float4s
static constexpr int CHUNK_BYTES = PAT4 * 16;        // 16 KB
static constexpr long long A_CHUNKS = 6144;          // first 96 MiB: evict_last

__device__ __forceinline__ uint32_t smem_u32(const void* p) {
    uint32_t a;
    asm("{ .reg .u64 t; cvta.to.shared.u64 t, %1; cvt.u32.u64 %0, t; }"
        : "=r"(a) : "l"(p));
    return a;
}

__global__ __launch_bounds__(THREADS, 1)
void fill_periodic_tma_kernel(const float* __restrict__ bits,
                              char* __restrict__ out,
                              long long n_chunks)
{
    __shared__ float4 pat[PAT4];   // 16 KB

    const float4* bits4 = reinterpret_cast<const float4*>(bits);
    for (int i = threadIdx.x; i < PAT4; i += THREADS) {
        float4 b = bits4[i];
        float4 v;
        v.x = (fabsf(b.x) > 0.5f) ? 1.0f : 0.0f;
        v.y = (fabsf(b.y) > 0.5f) ? 1.0f : 0.0f;
        v.z = (fabsf(b.z) > 0.5f) ? 1.0f : 0.0f;
        v.w = (fabsf(b.w) > 0.5f) ? 1.0f : 0.0f;
        pat[i] = v;
    }
    __syncthreads();
    asm volatile("fence.proxy.async.shared::cta;" ::: "memory");

    if (threadIdx.x == 0) {
        uint32_t saddr = smem_u32(pat);

        uint64_t pol_last, pol_first;
        asm("createpolicy.fractional.L2::evict_last.b64 %0, 1.0;"
            : "=l"(pol_last));
        asm("createpolicy.fractional.L2::evict_first.b64 %0, 1.0;"
            : "=l"(pol_first));

        for (long long c = blockIdx.x; c < n_chunks; c += gridDim.x) {
            char* g = out + c * (long long)CHUNK_BYTES;
            uint64_t pol = (c < A_CHUNKS) ? pol_last : pol_first;
            asm volatile(
                "cp.async.bulk.global.shared::cta.bulk_group.L2::cache_hint"
                " [%0], [%1], %2, %3;"
                :: "l"(g), "r"(saddr), "n"(CHUNK_BYTES), "l"(pol) : "memory");
        }
        asm volatile("cp.async.bulk.commit_group;" ::: "memory");
        asm volatile("cp.async.bulk.wait_group 0;" ::: "memory");
    }
}

extern "C" void kernel_launch(void* const* d_in, const int* in_sizes, int n_in,
                              void* d_out, int out_size)
{
    const float* bits = (const float*)d_in[0];
    long long total_bytes = (long long)out_size * 4;      // 192 MiB
    long long n_chunks = total_bytes / CHUNK_BYTES;       // 12288

    fill_periodic_tma_kernel<<<BLOCKS, THREADS>>>(bits, (char*)d_out, n_chunks);
}

// round 14
// speedup vs baseline: 1.0073x; 1.0073x over previous
#include <cuda_runtime.h>
#include <stdint.h>

// out[j] = (|bits[j % 4096]| > 0.5) ? 1.0f : 0.0f for all j in [0, 48*2^20).
// 192 MiB output = 16 KB-periodic pattern. Build the 16 KB pattern in SMEM,
// then blast it to GMEM with TMA bulk stores (SMEM->L2->HBM, bypasses L1).
//
// ROOFLINE NOTE: four structurally different store paths (STG.128 loop, TMA
// 128KB/16KB chunks, L2-residency-partitioned TMA) all converge on ~31.8us.
// 201 MB ingress / 31.8 us = 6.3 TB/s = the measured full-chip LTS write-
// ingress cap (path-independent, ~6300 B/cyc). This kernel is at that cap.
// evict_first keeps the stream FIFO-like in L2 for clean DRAM drain between
// graph replays; chunks are issued from two warps to halve the issue ramp.

static constexpr int THREADS     = 512;
static constexpr int BLOCKS      = 152;              // one block per SM
static constexpr int PAT4        = 1024;             // 16 KB pattern in float4s
static constexpr int CHUNK_BYTES = PAT4 * 16;        // 16 KB

__device__ __forceinline__ uint32_t smem_u32(const void* p) {
    uint32_t a;
    asm("{ .reg .u64 t; cvta.to.shared.u64 t, %1; cvt.u32.u64 %0, t; }"
        : "=r"(a) : "l"(p));
    return a;
}

__global__ __launch_bounds__(THREADS, 1)
void fill_periodic_tma_kernel(const float* __restrict__ bits,
                              char* __restrict__ out,
                              long long n_chunks)
{
    __shared__ float4 pat[PAT4];   // 16 KB

    // Build the pattern (2 iterations per thread).
    const float4* bits4 = reinterpret_cast<const float4*>(bits);
    for (int i = threadIdx.x; i < PAT4; i += THREADS) {
        float4 b = bits4[i];
        float4 v;
        v.x = (fabsf(b.x) > 0.5f) ? 1.0f : 0.0f;
        v.y = (fabsf(b.y) > 0.5f) ? 1.0f : 0.0f;
        v.z = (fabsf(b.z) > 0.5f) ? 1.0f : 0.0f;
        v.w = (fabsf(b.w) > 0.5f) ? 1.0f : 0.0f;
        pat[i] = v;
    }
    __syncthreads();
    // Order generic-proxy SMEM writes before async-proxy (TMA) reads.
    asm volatile("fence.proxy.async.shared::cta;" ::: "memory");

    // Two issuing threads per block (lane 0 of warps 0 and 1); each covers
    // every other chunk of this block's stripe. Halves the serial issue ramp.
    const int wid = threadIdx.x >> 5;
    if ((threadIdx.x & 31) == 0 && wid < 2) {
        uint32_t saddr = smem_u32(pat);
        uint64_t pol;
        asm("createpolicy.fractional.L2::evict_first.b64 %0, 1.0;" : "=l"(pol));

        const long long step = 2LL * gridDim.x;
        for (long long c = blockIdx.x + (long long)wid * gridDim.x;
             c < n_chunks; c += step) {
            char* g = out + c * (long long)CHUNK_BYTES;
            asm volatile(
                "cp.async.bulk.global.shared::cta.bulk_group.L2::cache_hint"
                " [%0], [%1], %2, %3;"
                :: "l"(g), "r"(saddr), "n"(CHUNK_BYTES), "l"(pol) : "memory");
        }
        asm volatile("cp.async.bulk.commit_group;" ::: "memory");
        asm volatile("cp.async.bulk.wait_group 0;" ::: "memory");
    }
}

extern "C" void kernel_launch(void* const* d_in, const int* in_sizes, int n_in,
                              void* d_out, int out_size)
{
    const float* bits = (const float*)d_in[0];
    long long total_bytes = (long long)out_size * 4;      // 192 MiB
    long long n_chunks = total_bytes / CHUNK_BYTES;       // 12288

    fill_periodic_tma_kernel<<<BLOCKS, THREADS>>>(bits, (char*)d_out, n_chunks);
}